// round 3
// baseline (speedup 1.0000x reference)
#include <cuda_runtime.h>
#include <cuda_bf16.h>
#include <cstdint>

#define NUM_USERS 100000
#define NUM_ITEMS 50000
#define IN_DIM    128
#define HID_DIM   256
#define OUT_DIM   64
#define RLEV      5
#define NEDGE     300000
#define EPSV      1e-10f

// ---------------- scratch (static __device__, no allocation) ----------------
__device__ float d_Wcu[IN_DIM * RLEV * OUT_DIM];   // folded item->user weights, [k][r*64+n]
__device__ float d_Wcv[IN_DIM * RLEV * OUT_DIM];   // folded user->item weights
__device__ float d_invdu[NUM_USERS];
__device__ float d_invdv[NUM_ITEMS];
__device__ float d_Yu[(size_t)NUM_USERS * RLEV * OUT_DIM];  // [u][r*64+n], 128MB
__device__ float d_Yv[(size_t)NUM_ITEMS * RLEV * OUT_DIM];  // 64MB
__device__ float d_Mu[(size_t)NUM_USERS * OUT_DIM];         // 25.6MB
__device__ float d_Mv[(size_t)NUM_ITEMS * OUT_DIM];         // 12.8MB

// ---------------- kernel 0: zero accumulators + inverse sqrt degrees ----------------
__global__ void init_kernel(const float* __restrict__ deg_u,
                            const float* __restrict__ deg_v) {
    int idx = blockIdx.x * blockDim.x + threadIdx.x;
    const int nu4 = NUM_USERS * (OUT_DIM / 4);         // 1,600,000
    const int nv4 = NUM_ITEMS * (OUT_DIM / 4);         // 800,000
    float4 z = make_float4(0.f, 0.f, 0.f, 0.f);
    if (idx < nu4) {
        ((float4*)d_Mu)[idx] = z;
    } else if (idx < nu4 + nv4) {
        ((float4*)d_Mv)[idx - nu4] = z;
    }
    // degrees piggyback on the same (much larger) grid
    if (idx < NUM_USERS) {
        d_invdu[idx] = rsqrtf(fmaxf(__ldg(deg_u + idx), EPSV));
    } else if (idx < NUM_USERS + NUM_ITEMS) {
        int j = idx - NUM_USERS;
        d_invdv[j] = rsqrtf(fmaxf(__ldg(deg_v + j), EPSV));
    }
}

// ---------------- kernel 1: Wc[r] = W1[r] @ W2  (fold output layer) ----------------
// W1: [R,128,256]  W2: [256,64]  ->  Wc stored [k][r*64+n] (stride 320)
__global__ void wc_kernel(const float* __restrict__ W1u, const float* __restrict__ W2u,
                          const float* __restrict__ W1v, const float* __restrict__ W2v) {
    int n = threadIdx.x;          // 0..63
    int k = blockIdx.x;           // 0..127
    int r = blockIdx.y;           // 0..4
    const float* W1 = blockIdx.z ? W1v : W1u;
    const float* W2 = blockIdx.z ? W2v : W2u;
    float* Wc       = blockIdx.z ? d_Wcv : d_Wcu;
    const float* w1row = W1 + ((size_t)r * IN_DIM + k) * HID_DIM;
    float acc = 0.f;
#pragma unroll 8
    for (int h = 0; h < HID_DIM; ++h)
        acc += __ldg(w1row + h) * __ldg(W2 + h * OUT_DIM + n);
    Wc[k * (RLEV * OUT_DIM) + r * OUT_DIM + n] = acc;
}

// ---------------- kernel 2: node transform  Y = (X @ Wc) * inv_deg ----------------
// Yu[u] = (X_u[u] @ Wc_user2item) / sqrt(du)  : messages FROM user u (per r slice)
// Yv[v] = (X_v[v] @ Wc_item2user) / sqrt(dv)  : messages FROM item v (per r slice)
// BM=128, BN=64 (one r-slice per block.y), full K=128 resident. fp32x2 packed FMA.
#define GEMM_SMEM_BYTES ((128 * 129 + 128 * 64) * 4)

__global__ __launch_bounds__(128)
void gemm_y_kernel(const float* __restrict__ X, int which, int M) {
    extern __shared__ float smem[];
    float* Xs = smem;               // [128][129] padded
    float* Ws = smem + 128 * 129;   // [128][64]

    const float* Wg  = which ? d_Wcu  : d_Wcv;
    const float* inv = which ? d_invdv : d_invdu;
    float*       Y   = which ? d_Yv   : d_Yu;

    const int tid  = threadIdx.x;
    const int row0 = blockIdx.x * 128;
    const int r    = blockIdx.y;

    // load X tile: 128 rows x 128 k (coalesced float4 along k)
#pragma unroll
    for (int p = 0; p < 32; ++p) {
        int f   = tid + p * 128;        // float4 linear index 0..4095
        int row = f >> 5;
        int k4  = f & 31;
        float4 x = make_float4(0.f, 0.f, 0.f, 0.f);
        int grow = row0 + row;
        if (grow < M) x = *(const float4*)(X + (size_t)grow * IN_DIM + k4 * 4);
        float* dst = Xs + row * 129 + k4 * 4;
        dst[0] = x.x; dst[1] = x.y; dst[2] = x.z; dst[3] = x.w;
    }
    // load W tile: 128 k x 64 n for this r-slice
#pragma unroll
    for (int p = 0; p < 16; ++p) {
        int f  = tid + p * 128;         // 0..2047
        int k  = f >> 4;
        int n4 = f & 15;
        *(float4*)(Ws + k * 64 + n4 * 4) =
            *(const float4*)(Wg + k * (RLEV * OUT_DIM) + r * OUT_DIM + n4 * 4);
    }
    __syncthreads();

    const int tc = tid & 7;     // 8 col-groups of 8
    const int tr = tid >> 3;    // 16 row-groups of 8

    unsigned long long acc[8][4];
#pragma unroll
    for (int i = 0; i < 8; ++i)
#pragma unroll
        for (int j = 0; j < 4; ++j) acc[i][j] = 0ULL;

    const float* xbase = Xs + (tr * 8) * 129;
    const float* wbase = Ws + tc * 8;

#pragma unroll 4
    for (int k = 0; k < 128; ++k) {
        ulonglong2 wa = *(const ulonglong2*)(wbase + k * 64);      // cols 0..3
        ulonglong2 wb = *(const ulonglong2*)(wbase + k * 64 + 4);  // cols 4..7
#pragma unroll
        for (int i = 0; i < 8; ++i) {
            float a = xbase[i * 129 + k];
            unsigned long long a2;
            asm("mov.b64 %0, {%1, %1};" : "=l"(a2) : "f"(a));
            asm("fma.rn.f32x2 %0, %1, %2, %0;" : "+l"(acc[i][0]) : "l"(a2), "l"(wa.x));
            asm("fma.rn.f32x2 %0, %1, %2, %0;" : "+l"(acc[i][1]) : "l"(a2), "l"(wa.y));
            asm("fma.rn.f32x2 %0, %1, %2, %0;" : "+l"(acc[i][2]) : "l"(a2), "l"(wb.x));
            asm("fma.rn.f32x2 %0, %1, %2, %0;" : "+l"(acc[i][3]) : "l"(a2), "l"(wb.y));
        }
    }

    // epilogue: scale by inv_deg[row], write Y[row][r*64 + tc*8 .. +7]
#pragma unroll
    for (int i = 0; i < 8; ++i) {
        int row = row0 + tr * 8 + i;
        if (row < M) {
            float s = inv[row];
            float x0, x1, x2, x3, x4, x5, x6, x7;
            asm("mov.b64 {%0, %1}, %2;" : "=f"(x0), "=f"(x1) : "l"(acc[i][0]));
            asm("mov.b64 {%0, %1}, %2;" : "=f"(x2), "=f"(x3) : "l"(acc[i][1]));
            asm("mov.b64 {%0, %1}, %2;" : "=f"(x4), "=f"(x5) : "l"(acc[i][2]));
            asm("mov.b64 {%0, %1}, %2;" : "=f"(x6), "=f"(x7) : "l"(acc[i][3]));
            float* yp = Y + (size_t)row * (RLEV * OUT_DIM) + r * OUT_DIM + tc * 8;
            *(float4*)(yp)     = make_float4(x0 * s, x1 * s, x2 * s, x3 * s);
            *(float4*)(yp + 4) = make_float4(x4 * s, x5 * s, x6 * s, x7 * s);
        }
    }
}

// ---------------- kernel 3: edge scatter (one warp per edge, both directions) ----------------
__global__ __launch_bounds__(512)
void scatter_kernel(const int* __restrict__ u_idx,
                    const int* __restrict__ v_idx) {
    unsigned int wid = (blockIdx.x * blockDim.x + threadIdx.x) >> 5;  // edge id in [0, R*E)
    if (wid >= (unsigned)(RLEV * NEDGE)) return;
    int lane = threadIdx.x & 31;
    unsigned int r = wid / (unsigned)NEDGE;   // const divisor -> mul/shift
    int u = __ldg(u_idx + wid);
    int v = __ldg(v_idx + wid);
    int l = lane & 15;

    const float* src;
    float* dst;
    if (lane < 16) {  // message item v -> user u : gather Yv[v] slice r, scatter Mu[u]
        src = d_Yv + (size_t)v * (RLEV * OUT_DIM) + r * OUT_DIM;
        dst = d_Mu + (size_t)u * OUT_DIM;
    } else {          // message user u -> item v : gather Yu[u] slice r, scatter Mv[v]
        src = d_Yu + (size_t)u * (RLEV * OUT_DIM) + r * OUT_DIM;
        dst = d_Mv + (size_t)v * OUT_DIM;
    }
    float4 val = __ldg((const float4*)(src) + l);
    asm volatile("red.global.add.v4.f32 [%0], {%1,%2,%3,%4};"
                 :: "l"(dst + l * 4), "f"(val.x), "f"(val.y), "f"(val.z), "f"(val.w)
                 : "memory");
}

// ---------------- kernel 4: epilogue  h = relu(M * inv_deg + b) ----------------
__global__ void epilogue_kernel(const float* __restrict__ bu,
                                const float* __restrict__ bv,
                                float* __restrict__ out) {
    int idx = blockIdx.x * blockDim.x + threadIdx.x;  // float4 index
    const int nu4 = NUM_USERS * (OUT_DIM / 4);
    const int nv4 = NUM_ITEMS * (OUT_DIM / 4);
    if (idx < nu4) {
        int u  = idx >> 4;
        int c4 = idx & 15;
        float4 m = ((const float4*)d_Mu)[idx];
        float  s = d_invdu[u];
        float4 b = __ldg((const float4*)bu + c4);
        float4 h;
        h.x = fmaxf(fmaf(m.x, s, b.x), 0.f);
        h.y = fmaxf(fmaf(m.y, s, b.y), 0.f);
        h.z = fmaxf(fmaf(m.z, s, b.z), 0.f);
        h.w = fmaxf(fmaf(m.w, s, b.w), 0.f);
        ((float4*)out)[idx] = h;
    } else if (idx < nu4 + nv4) {
        int j  = idx - nu4;
        int v  = j >> 4;
        int c4 = j & 15;
        float4 m = ((const float4*)d_Mv)[j];
        float  s = d_invdv[v];
        float4 b = __ldg((const float4*)bv + c4);
        float4 h;
        h.x = fmaxf(fmaf(m.x, s, b.x), 0.f);
        h.y = fmaxf(fmaf(m.y, s, b.y), 0.f);
        h.z = fmaxf(fmaf(m.z, s, b.z), 0.f);
        h.w = fmaxf(fmaf(m.w, s, b.w), 0.f);
        ((float4*)out)[idx] = h;
    }
}

// ---------------- launch ----------------
extern "C" void kernel_launch(void* const* d_in, const int* in_sizes, int n_in,
                              void* d_out, int out_size) {
    const int*   u_idx  = (const int*)d_in[0];     // [R,E]
    const int*   v_idx  = (const int*)d_in[1];     // [R,E]
    const float* deg_u  = (const float*)d_in[2];   // [NU]
    const float* deg_v  = (const float*)d_in[3];   // [NI]
    const float* X_u    = (const float*)d_in[4];   // [NU,128]
    const float* X_v    = (const float*)d_in[5];   // [NI,128]
    const float* W_i2u  = (const float*)d_in[6];   // [R,128,256]
    const float* W_u2i  = (const float*)d_in[7];   // [R,128,256]
    const float* Wo_u   = (const float*)d_in[8];   // [256,64]
    const float* bo_u   = (const float*)d_in[9];   // [64]
    const float* Wo_v   = (const float*)d_in[10];  // [256,64]
    const float* bo_v   = (const float*)d_in[11];  // [64]
    float* out = (float*)d_out;

    // zero accumulators + degrees
    init_kernel<<<(2400000 + 255) / 256, 256>>>(deg_u, deg_v);

    // folded weights Wc[r] = W1[r] @ W2
    wc_kernel<<<dim3(IN_DIM, RLEV, 2), OUT_DIM>>>(W_i2u, Wo_u, W_u2i, Wo_v);

    // node transforms (fp32x2 GEMM)
    cudaFuncSetAttribute(gemm_y_kernel, cudaFuncAttributeMaxDynamicSharedMemorySize,
                         GEMM_SMEM_BYTES);
    gemm_y_kernel<<<dim3((NUM_USERS + 127) / 128, RLEV), 128, GEMM_SMEM_BYTES>>>(
        X_u, 0, NUM_USERS);
    gemm_y_kernel<<<dim3((NUM_ITEMS + 127) / 128, RLEV), 128, GEMM_SMEM_BYTES>>>(
        X_v, 1, NUM_ITEMS);

    // edge scatter: 1 warp per edge, 16 warps per block
    const int n_edges = RLEV * NEDGE;
    scatter_kernel<<<(n_edges + 15) / 16, 512>>>(u_idx, v_idx);

    // epilogue
    epilogue_kernel<<<(2400000 + 255) / 256, 256>>>(bo_u, bo_v, out);
}

// round 6
// speedup vs baseline: 1.0257x; 1.0257x over previous
#include <cuda_runtime.h>
#include <cuda_bf16.h>
#include <cstdint>

#define NUM_USERS 100000
#define NUM_ITEMS 50000
#define IN_DIM    128
#define HID_DIM   256
#define OUT_DIM   64
#define RLEV      5
#define NEDGE     300000
#define EPSV      1e-10f

// ---------------- scratch (static __device__, no allocation) ----------------
__device__ float d_Wcu[IN_DIM * RLEV * OUT_DIM];   // folded item->user weights, [k][r*64+n]
__device__ float d_Wcv[IN_DIM * RLEV * OUT_DIM];   // folded user->item weights
__device__ float d_invdu[NUM_USERS];
__device__ float d_invdv[NUM_ITEMS];
__device__ float d_Yu[(size_t)NUM_USERS * RLEV * OUT_DIM];  // [u][r*64+n], 128MB
__device__ float d_Yv[(size_t)NUM_ITEMS * RLEV * OUT_DIM];  // 64MB
__device__ float d_Mu[(size_t)NUM_USERS * OUT_DIM];         // 25.6MB
__device__ float d_Mv[(size_t)NUM_ITEMS * OUT_DIM];         // 12.8MB

// ---------------- kernel 0: zero accumulators + inverse sqrt degrees ----------------
__global__ void init_kernel(const float* __restrict__ deg_u,
                            const float* __restrict__ deg_v) {
    int idx = blockIdx.x * blockDim.x + threadIdx.x;
    const int nu4 = NUM_USERS * (OUT_DIM / 4);         // 1,600,000
    const int nv4 = NUM_ITEMS * (OUT_DIM / 4);         // 800,000
    float4 z = make_float4(0.f, 0.f, 0.f, 0.f);
    if (idx < nu4) {
        ((float4*)d_Mu)[idx] = z;
    } else if (idx < nu4 + nv4) {
        ((float4*)d_Mv)[idx - nu4] = z;
    }
    if (idx < NUM_USERS) {
        d_invdu[idx] = rsqrtf(fmaxf(__ldg(deg_u + idx), EPSV));
    } else if (idx < NUM_USERS + NUM_ITEMS) {
        int j = idx - NUM_USERS;
        d_invdv[j] = rsqrtf(fmaxf(__ldg(deg_v + j), EPSV));
    }
}

// ---------------- kernel 1: Wc[r] = W1[r] @ W2  (fold output layer) ----------------
__global__ void wc_kernel(const float* __restrict__ W1u, const float* __restrict__ W2u,
                          const float* __restrict__ W1v, const float* __restrict__ W2v) {
    int n = threadIdx.x;          // 0..63
    int k = blockIdx.x;           // 0..127
    int r = blockIdx.y;           // 0..4
    const float* W1 = blockIdx.z ? W1v : W1u;
    const float* W2 = blockIdx.z ? W2v : W2u;
    float* Wc       = blockIdx.z ? d_Wcv : d_Wcu;
    const float* w1row = W1 + ((size_t)r * IN_DIM + k) * HID_DIM;
    float acc = 0.f;
#pragma unroll 8
    for (int h = 0; h < HID_DIM; ++h)
        acc += __ldg(w1row + h) * __ldg(W2 + h * OUT_DIM + n);
    Wc[k * (RLEV * OUT_DIM) + r * OUT_DIM + n] = acc;
}

// ---------------- kernel 2: node transform  Y = (X @ Wc) * inv_deg ----------------
// Yu[u] = (X_u[u] @ Wc_user2item) / sqrt(du)
// Yv[v] = (X_v[v] @ Wc_item2user) / sqrt(dv)
// BM=128, BN=64 (one r-slice per block.y). X row stride padded to 132 floats so
// k-direction LDS are 16B-aligned LDS.128 (4 k-values per request).
#define XPAD 132
#define GEMM_SMEM_BYTES ((128 * XPAD + 128 * 64) * 4)

__global__ __launch_bounds__(128)
void gemm_y_kernel(const float* __restrict__ X, int which, int M) {
    extern __shared__ float smem[];
    float* Xs = smem;                  // [128][XPAD]
    float* Ws = smem + 128 * XPAD;     // [128][64]

    const float* Wg  = which ? d_Wcu  : d_Wcv;
    const float* inv = which ? d_invdv : d_invdu;
    float*       Y   = which ? d_Yv   : d_Yu;

    const int tid  = threadIdx.x;
    const int row0 = blockIdx.x * 128;
    const int r    = blockIdx.y;

    // load X tile: 128 rows x 128 k. Coalesced gmem float4, conflict-free STS.128.
#pragma unroll
    for (int p = 0; p < 32; ++p) {
        int f   = tid + p * 128;        // float4 linear index 0..4095
        int row = f >> 5;
        int k4  = f & 31;
        float4 x = make_float4(0.f, 0.f, 0.f, 0.f);
        int grow = row0 + row;
        if (grow < M) x = *(const float4*)(X + (size_t)grow * IN_DIM + k4 * 4);
        *(float4*)(Xs + row * XPAD + k4 * 4) = x;
    }
    // load W tile: 128 k x 64 n for this r-slice
#pragma unroll
    for (int p = 0; p < 16; ++p) {
        int f  = tid + p * 128;         // 0..2047
        int k  = f >> 4;
        int n4 = f & 15;
        *(float4*)(Ws + k * 64 + n4 * 4) =
            *(const float4*)(Wg + k * (RLEV * OUT_DIM) + r * OUT_DIM + n4 * 4);
    }
    __syncthreads();

    const int tc = tid & 7;     // 8 col-groups of 8
    const int tr = tid >> 3;    // 16 row-groups of 8

    unsigned long long acc[8][4];
#pragma unroll
    for (int i = 0; i < 8; ++i)
#pragma unroll
        for (int j = 0; j < 4; ++j) acc[i][j] = 0ULL;

    const float* xbase = Xs + (tr * 8) * XPAD;
    const float* wbase = Ws + tc * 8;

    for (int k0 = 0; k0 < 128; k0 += 4) {
        // one LDS.128 per row caches 4 k-values
        float4 xv[8];
#pragma unroll
        for (int i = 0; i < 8; ++i)
            xv[i] = *(const float4*)(xbase + i * XPAD + k0);
#pragma unroll
        for (int kk = 0; kk < 4; ++kk) {
            ulonglong2 wa = *(const ulonglong2*)(wbase + (k0 + kk) * 64);      // cols 0..3
            ulonglong2 wb = *(const ulonglong2*)(wbase + (k0 + kk) * 64 + 4);  // cols 4..7
#pragma unroll
            for (int i = 0; i < 8; ++i) {
                float a = (kk == 0) ? xv[i].x : (kk == 1) ? xv[i].y
                        : (kk == 2) ? xv[i].z : xv[i].w;
                unsigned long long a2;
                asm("mov.b64 %0, {%1, %1};" : "=l"(a2) : "f"(a));
                asm("fma.rn.f32x2 %0, %1, %2, %0;" : "+l"(acc[i][0]) : "l"(a2), "l"(wa.x));
                asm("fma.rn.f32x2 %0, %1, %2, %0;" : "+l"(acc[i][1]) : "l"(a2), "l"(wa.y));
                asm("fma.rn.f32x2 %0, %1, %2, %0;" : "+l"(acc[i][2]) : "l"(a2), "l"(wb.x));
                asm("fma.rn.f32x2 %0, %1, %2, %0;" : "+l"(acc[i][3]) : "l"(a2), "l"(wb.y));
            }
        }
    }

    // epilogue: scale by inv_deg[row], write Y[row][r*64 + tc*8 .. +7]
#pragma unroll
    for (int i = 0; i < 8; ++i) {
        int row = row0 + tr * 8 + i;
        if (row < M) {
            float s = inv[row];
            float x0, x1, x2, x3, x4, x5, x6, x7;
            asm("mov.b64 {%0, %1}, %2;" : "=f"(x0), "=f"(x1) : "l"(acc[i][0]));
            asm("mov.b64 {%0, %1}, %2;" : "=f"(x2), "=f"(x3) : "l"(acc[i][1]));
            asm("mov.b64 {%0, %1}, %2;" : "=f"(x4), "=f"(x5) : "l"(acc[i][2]));
            asm("mov.b64 {%0, %1}, %2;" : "=f"(x6), "=f"(x7) : "l"(acc[i][3]));
            float* yp = Y + (size_t)row * (RLEV * OUT_DIM) + r * OUT_DIM + tc * 8;
            *(float4*)(yp)     = make_float4(x0 * s, x1 * s, x2 * s, x3 * s);
            *(float4*)(yp + 4) = make_float4(x4 * s, x5 * s, x6 * s, x7 * s);
        }
    }
}

// ---------------- kernel 3: edge scatter (one warp per edge, both directions) ----------------
__global__ __launch_bounds__(512)
void scatter_kernel(const int* __restrict__ u_idx,
                    const int* __restrict__ v_idx) {
    unsigned int wid = (blockIdx.x * blockDim.x + threadIdx.x) >> 5;  // edge id in [0, R*E)
    if (wid >= (unsigned)(RLEV * NEDGE)) return;
    int lane = threadIdx.x & 31;
    unsigned int r = wid / (unsigned)NEDGE;
    int u = __ldg(u_idx + wid);
    int v = __ldg(v_idx + wid);
    int l = lane & 15;

    const float* src;
    float* dst;
    if (lane < 16) {  // item v -> user u
        src = d_Yv + (size_t)v * (RLEV * OUT_DIM) + r * OUT_DIM;
        dst = d_Mu + (size_t)u * OUT_DIM;
    } else {          // user u -> item v
        src = d_Yu + (size_t)u * (RLEV * OUT_DIM) + r * OUT_DIM;
        dst = d_Mv + (size_t)v * OUT_DIM;
    }
    float4 val = __ldg((const float4*)(src) + l);
    asm volatile("red.global.add.v4.f32 [%0], {%1,%2,%3,%4};"
                 :: "l"(dst + l * 4), "f"(val.x), "f"(val.y), "f"(val.z), "f"(val.w)
                 : "memory");
}

// ---------------- kernel 4: epilogue  h = relu(M * inv_deg + b) ----------------
__global__ void epilogue_kernel(const float* __restrict__ bu,
                                const float* __restrict__ bv,
                                float* __restrict__ out) {
    int idx = blockIdx.x * blockDim.x + threadIdx.x;  // float4 index
    const int nu4 = NUM_USERS * (OUT_DIM / 4);
    const int nv4 = NUM_ITEMS * (OUT_DIM / 4);
    if (idx < nu4) {
        int u  = idx >> 4;
        int c4 = idx & 15;
        float4 m = ((const float4*)d_Mu)[idx];
        float  s = d_invdu[u];
        float4 b = __ldg((const float4*)bu + c4);
        float4 h;
        h.x = fmaxf(fmaf(m.x, s, b.x), 0.f);
        h.y = fmaxf(fmaf(m.y, s, b.y), 0.f);
        h.z = fmaxf(fmaf(m.z, s, b.z), 0.f);
        h.w = fmaxf(fmaf(m.w, s, b.w), 0.f);
        ((float4*)out)[idx] = h;
    } else if (idx < nu4 + nv4) {
        int j  = idx - nu4;
        int v  = j >> 4;
        int c4 = j & 15;
        float4 m = ((const float4*)d_Mv)[j];
        float  s = d_invdv[v];
        float4 b = __ldg((const float4*)bv + c4);
        float4 h;
        h.x = fmaxf(fmaf(m.x, s, b.x), 0.f);
        h.y = fmaxf(fmaf(m.y, s, b.y), 0.f);
        h.z = fmaxf(fmaf(m.z, s, b.z), 0.f);
        h.w = fmaxf(fmaf(m.w, s, b.w), 0.f);
        ((float4*)out)[idx] = h;
    }
}

// ---------------- launch ----------------
extern "C" void kernel_launch(void* const* d_in, const int* in_sizes, int n_in,
                              void* d_out, int out_size) {
    const int*   u_idx  = (const int*)d_in[0];     // [R,E]
    const int*   v_idx  = (const int*)d_in[1];     // [R,E]
    const float* deg_u  = (const float*)d_in[2];   // [NU]
    const float* deg_v  = (const float*)d_in[3];   // [NI]
    const float* X_u    = (const float*)d_in[4];   // [NU,128]
    const float* X_v    = (const float*)d_in[5];   // [NI,128]
    const float* W_i2u  = (const float*)d_in[6];   // [R,128,256]
    const float* W_u2i  = (const float*)d_in[7];   // [R,128,256]
    const float* Wo_u   = (const float*)d_in[8];   // [256,64]
    const float* bo_u   = (const float*)d_in[9];   // [64]
    const float* Wo_v   = (const float*)d_in[10];  // [256,64]
    const float* bo_v   = (const float*)d_in[11];  // [64]
    float* out = (float*)d_out;

    init_kernel<<<(2400000 + 255) / 256, 256>>>(deg_u, deg_v);
    wc_kernel<<<dim3(IN_DIM, RLEV, 2), OUT_DIM>>>(W_i2u, Wo_u, W_u2i, Wo_v);

    cudaFuncSetAttribute(gemm_y_kernel, cudaFuncAttributeMaxDynamicSharedMemorySize,
                         GEMM_SMEM_BYTES);
    gemm_y_kernel<<<dim3((NUM_USERS + 127) / 128, RLEV), 128, GEMM_SMEM_BYTES>>>(
        X_u, 0, NUM_USERS);
    gemm_y_kernel<<<dim3((NUM_ITEMS + 127) / 128, RLEV), 128, GEMM_SMEM_BYTES>>>(
        X_v, 1, NUM_ITEMS);

    const int n_edges = RLEV * NEDGE;
    scatter_kernel<<<(n_edges + 15) / 16, 512>>>(u_idx, v_idx);

    epilogue_kernel<<<(2400000 + 255) / 256, 256>>>(bo_u, bo_v, out);
}